// round 13
// baseline (speedup 1.0000x reference)
#include <cuda_runtime.h>
#include <cuda_fp16.h>
#include <math.h>
#include <stdint.h>

#define Bb 2
#define Tt 1024
#define Dd 768
#define Hh 3072
#define Ee 8
#define Nn (Bb*Tt)      // 2048 tokens
#define NK (Nn*2)       // 4096 assignments
#define CAP Nn          // slots per expert

// ---------------- scratch (device globals) ----------------------------------
__device__ __half g_hh[(size_t)Ee * CAP * Hh];   // gelu(x@W1), fp16, slot rows
__device__ float  g_y[(size_t)Ee * CAP * Dd];    // h@W2, slot rows
__device__ __half g_xh[(size_t)Nn * Dd];         // fp16 x
__device__ __half g_w1h[(size_t)Ee * Dd * Hh];
__device__ __half g_w2h[(size_t)Ee * Dd * Hh];
__device__ int   g_counts[Ee];                   // zero at entry; reset by combine
__device__ float g_topw[NK];
__device__ int   g_slot_tok[Ee * CAP];
__device__ int   g_tok_slot[NK];
__device__ float g_probsum[Ee];                  // zero at entry; reset by combine

// ---------------- helpers ----------------------------------------------------
__device__ __forceinline__ void cp16(uint32_t dst, const void* src, int pbytes) {
    asm volatile("cp.async.cg.shared.global [%0], [%1], 16, %2;"
                 :: "r"(dst), "l"(src), "r"(pbytes));
}
__device__ __forceinline__ void mma_f16(float c[4], uint32_t a0, uint32_t a1,
                                        uint32_t a2, uint32_t a3,
                                        uint32_t b0, uint32_t b1) {
    asm volatile(
        "mma.sync.aligned.m16n8k16.row.col.f32.f16.f16.f32 "
        "{%0,%1,%2,%3}, {%4,%5,%6,%7}, {%8,%9}, {%0,%1,%2,%3};"
        : "+f"(c[0]), "+f"(c[1]), "+f"(c[2]), "+f"(c[3])
        : "r"(a0), "r"(a1), "r"(a2), "r"(a3), "r"(b0), "r"(b1));
}
__device__ __forceinline__ void ldsm4(uint32_t a[4], uint32_t addr) {
    asm volatile("ldmatrix.sync.aligned.m8n8.x4.shared.b16 {%0,%1,%2,%3}, [%4];"
                 : "=r"(a[0]), "=r"(a[1]), "=r"(a[2]), "=r"(a[3]) : "r"(addr));
}
__device__ __forceinline__ void ldsm4t(uint32_t a[4], uint32_t addr) {
    asm volatile("ldmatrix.sync.aligned.m8n8.x4.trans.shared.b16 {%0,%1,%2,%3}, [%4];"
                 : "=r"(a[0]), "=r"(a[1]), "=r"(a[2]), "=r"(a[3]) : "r"(addr));
}
__device__ __forceinline__ float gelu_exact(float c) {
    return 0.5f * c * (1.f + erff(c * 0.7071067811865475f));
}
__device__ __forceinline__ uint32_t pack2(float a, float b) {
    __half2 h = __floats2half2_rn(a, b);
    return *reinterpret_cast<uint32_t*>(&h);
}
// convert one 16B quad (8 fp32 -> 8 fp16)
__device__ __forceinline__ void conv_quad(const float* __restrict__ src,
                                          __half* __restrict__ dst, long long q) {
    const float4* s = reinterpret_cast<const float4*>(src) + q * 2;
    float4 v0 = s[0], v1 = s[1];
    uint4 o;
    o.x = pack2(v0.x, v0.y); o.y = pack2(v0.z, v0.w);
    o.z = pack2(v1.x, v1.y); o.w = pack2(v1.z, v1.w);
    reinterpret_cast<uint4*>(dst)[q] = o;
}

// ---------------- routing (+x fp16, +W1 fp16) --------------------------------
__global__ void routing_kernel(const float* __restrict__ x,
                               const float* __restrict__ Wr,
                               const float* __restrict__ W1) {
    int n = blockIdx.x;
    int t = threadIdx.x;
    const float* xr = x + (size_t)n * Dd;
    float a0 = 0.f, a1 = 0.f, a2 = 0.f;
    for (int d = t; d < Dd; d += 128) {
        float xv = xr[d];
        g_xh[(size_t)n * Dd + d] = __float2half(xv);
        a0 += xv * Wr[d];
        a1 += xv * Wr[Dd + d];
        a2 += xv * Wr[2 * Dd + d];
    }
    __shared__ float s0[128], s1[128], s2[128];
    s0[t] = a0; s1[t] = a1; s2[t] = a2;
    __syncthreads();
    for (int off = 64; off > 0; off >>= 1) {
        if (t < off) { s0[t] += s0[t+off]; s1[t] += s1[t+off]; s2[t] += s2[t+off]; }
        __syncthreads();
    }
    if (t == 0) {
        float z0 = s0[0], z1 = s1[0], z2 = s2[0];
        const float inv3 = 0.57735026918962576f;
        float logits[Ee];
        #pragma unroll
        for (int e = 0; e < Ee; e++) {
            float d0 = (e & 4) ? 1.f : -1.f;
            float d1 = (e & 2) ? 1.f : -1.f;
            float d2 = (e & 1) ? 1.f : -1.f;
            logits[e] = (d0 * z0 + d1 * z1 + d2 * z2) * inv3;
        }
        float m = logits[0];
        #pragma unroll
        for (int e = 1; e < Ee; e++) m = fmaxf(m, logits[e]);
        float p[Ee]; float sum = 0.f;
        #pragma unroll
        for (int e = 0; e < Ee; e++) { p[e] = expf(logits[e] - m); sum += p[e]; }
        float invs = 1.f / sum;
        #pragma unroll
        for (int e = 0; e < Ee; e++) atomicAdd(&g_probsum[e], p[e] * invs);
        int i0 = 0;
        #pragma unroll
        for (int e = 1; e < Ee; e++) if (p[e] > p[i0]) i0 = e;
        int i1 = (i0 == 0) ? 1 : 0;
        #pragma unroll
        for (int e = 0; e < Ee; e++) if (e != i0 && p[e] > p[i1]) i1 = e;
        float v0 = p[i0], v1 = p[i1];
        float wd = 1.f / (v0 + v1);
        g_topw[n*2]   = v0 * wd; g_topw[n*2+1] = v1 * wd;
        int pos0 = atomicAdd(&g_counts[i0], 1);
        int pos1 = atomicAdd(&g_counts[i1], 1);
        int slot0 = i0 * CAP + pos0;
        int slot1 = i1 * CAP + pos1;
        g_slot_tok[slot0] = n;  g_tok_slot[n*2]     = slot0;
        g_slot_tok[slot1] = n;  g_tok_slot[n*2 + 1] = slot1;
    }
    // convert this block's share of W1 to fp16 (hidden under DRAM-idle routing)
    long long qbase = (long long)n * 1152;
    #pragma unroll
    for (int q = 0; q < 9; q++)
        conv_quad(W1, g_w1h, qbase + q * 128 + t);
}

// ---------------- gemm1: 128x128, BK=32 (proven; also converts W2) -----------
#define NST 4

__global__ __launch_bounds__(256, 2) void gemm1_kernel(const __half* __restrict__ Wglob,
                                                       const float* __restrict__ W2src) {
    constexpr int A_BY = 128 * 64;
    constexpr int B_BY = 32 * 256;
    constexpr int NT   = Dd / 32;        // 24

    int t = threadIdx.x;
    {
        // convert this CTA's share of W2 (3072 CTAs x 768 quads)
        int bid = blockIdx.x + gridDim.x * (blockIdx.y + gridDim.y * blockIdx.z);
        long long qbase = (long long)bid * 768;
        #pragma unroll
        for (int q = 0; q < 3; q++)
            conv_quad(W2src, g_w2h, qbase + q * 256 + t);
    }

    int e = blockIdx.z;
    int cnt = g_counts[e];
    int m0 = blockIdx.y * 128;
    if (m0 >= cnt) return;
    int n0 = blockIdx.x * 128;
    int base = e * CAP + m0;
    int rows = min(128, cnt - m0);

    extern __shared__ char sm[];
    uint32_t uA = (uint32_t)__cvta_generic_to_shared(sm);
    uint32_t uB = uA + NST * A_BY;
    int* stok = (int*)(sm + NST * (A_BY + B_BY));

    int wid = t >> 5, lane = t & 31;
    int wm0 = (wid & 1) * 64, wn0 = (wid >> 1) * 32;
    int gid = lane >> 2, tig = lane & 3;

    int la_r = (lane & 7) + ((lane >> 3) & 1) * 8;
    int la_u = (lane >> 4) & 1;
    int lb_k = ((lane >> 3) & 1) * 8 + (lane & 7);
    int lb_n = ((lane >> 4) & 1) * 8;

    uint32_t a_base[4][2];
    #pragma unroll
    for (int mi = 0; mi < 4; mi++) {
        int r = wm0 + mi * 16 + la_r;
        #pragma unroll
        for (int ks = 0; ks < 2; ks++) {
            int u = 2 * ks + la_u;
            a_base[mi][ks] = uA + r * 64 + ((u ^ ((r >> 1) & 3)) << 4);
        }
    }
    uint32_t b_base[2];
    #pragma unroll
    for (int half = 0; half < 2; half++) {
        int ncol = wn0 + half * 16 + lb_n;
        int u = ncol >> 3;
        b_base[half] = uB + lb_k * 256 + ((u ^ (lb_k & 7)) << 4);
    }

    const __half* Wb = Wglob + (size_t)e * Dd * Hh;

    if (t < 128) stok[t] = (t < rows) ? g_slot_tok[base + t] : -1;
    __syncthreads();

    auto issue = [&](int kt) {
        int buf = kt & (NST - 1);
        uint32_t ab = uA + buf * A_BY;
        uint32_t bb = uB + buf * B_BY;
        #pragma unroll
        for (int i = 0; i < 2; i++) {
            int idx = i * 256 + t;
            int r = idx >> 2, u = idx & 3;
            uint32_t dst = ab + r * 64 + ((u ^ ((r >> 1) & 3)) << 4);
            int tok = stok[r];
            cp16(dst, g_xh + (size_t)max(tok, 0) * Dd + kt * 32 + u * 8,
                 (tok >= 0) ? 16 : 0);
        }
        #pragma unroll
        for (int i = 0; i < 2; i++) {
            int idx = i * 256 + t;
            int k = idx >> 4, u = idx & 15;
            uint32_t dst = bb + k * 256 + ((u ^ (k & 7)) << 4);
            cp16(dst, Wb + (size_t)(kt * 32 + k) * Hh + n0 + u * 8, 16);
        }
        asm volatile("cp.async.commit_group;" ::: "memory");
    };

    issue(0); issue(1); issue(2);

    float acc[4][4][4] = {};

    #pragma unroll 4
    for (int j = 0; j < NT; j++) {
        int buf = j & (NST - 1);
        if (j <= NT - 3)      asm volatile("cp.async.wait_group 2;" ::: "memory");
        else if (j == NT - 2) asm volatile("cp.async.wait_group 1;" ::: "memory");
        else                  asm volatile("cp.async.wait_group 0;" ::: "memory");
        __syncthreads();
        if (j + 3 < NT) issue(j + 3);

        uint32_t aoff = buf * A_BY;
        uint32_t boff = buf * B_BY;

        #pragma unroll
        for (int ks = 0; ks < 2; ks++) {
            uint32_t a[4][4];
            #pragma unroll
            for (int mi = 0; mi < 4; mi++)
                ldsm4(a[mi], a_base[mi][ks] + aoff);
            uint32_t b[2][4];
            #pragma unroll
            for (int half = 0; half < 2; half++)
                ldsm4t(b[half], b_base[half] + boff + ks * 4096);
            #pragma unroll
            for (int mi = 0; mi < 4; mi++)
                #pragma unroll
                for (int ni = 0; ni < 4; ni++)
                    mma_f16(acc[mi][ni], a[mi][0], a[mi][1], a[mi][2], a[mi][3],
                            b[ni >> 1][(ni & 1) * 2], b[ni >> 1][(ni & 1) * 2 + 1]);
        }
    }

    #pragma unroll
    for (int mi = 0; mi < 4; mi++) {
        int r0 = wm0 + mi * 16 + gid;
        #pragma unroll
        for (int ni = 0; ni < 4; ni++) {
            int c = n0 + wn0 + ni * 8 + tig * 2;
            #pragma unroll
            for (int half = 0; half < 2; half++) {
                int r = r0 + half * 8;
                if (r < rows)
                    *(__half2*)(g_hh + (size_t)(base + r) * Hh + c) =
                        __floats2half2_rn(gelu_exact(acc[mi][ni][half * 2]),
                                          gelu_exact(acc[mi][ni][half * 2 + 1]));
            }
        }
    }
}

// ---------------- gemm2: 64x128, BK=64 (halved sync count) -------------------
__global__ __launch_bounds__(256, 2) void gemm2_kernel(const __half* __restrict__ Wglob) {
    constexpr int A_BY = 64 * 128;       // 8 KB per stage (64 rows x 128B)
    constexpr int B_BY = 64 * 256;       // 16 KB per stage (64 rows x 256B)
    constexpr int NT   = Hh / 64;        // 48

    int e = blockIdx.z;
    int cnt = g_counts[e];
    int m0 = blockIdx.y * 64;
    if (m0 >= cnt) return;
    int n0 = blockIdx.x * 128;
    int base = e * CAP + m0;
    int rows = min(64, cnt - m0);

    extern __shared__ char sm[];
    uint32_t uA = (uint32_t)__cvta_generic_to_shared(sm);
    uint32_t uB = uA + NST * A_BY;

    int t = threadIdx.x, wid = t >> 5, lane = t & 31;
    int wm0 = (wid & 1) * 32, wn0 = (wid >> 1) * 32;
    int gid = lane >> 2, tig = lane & 3;

    int la_r = (lane & 7) + ((lane >> 3) & 1) * 8;
    int la_u = (lane >> 4) & 1;
    int lb_k = ((lane >> 3) & 1) * 8 + (lane & 7);
    int lb_n = ((lane >> 4) & 1) * 8;

    // A rows are 128B (BK=64), swizzle u ^ (r&7) on 16B units (round-6 layout)
    uint32_t a_base[2][4];
    #pragma unroll
    for (int mi = 0; mi < 2; mi++) {
        int r = wm0 + mi * 16 + la_r;
        #pragma unroll
        for (int ks = 0; ks < 4; ks++) {
            int u = 2 * ks + la_u;
            a_base[mi][ks] = uA + r * 128 + ((u ^ (r & 7)) << 4);
        }
    }
    uint32_t b_base[2];
    #pragma unroll
    for (int half = 0; half < 2; half++) {
        int ncol = wn0 + half * 16 + lb_n;
        int u = ncol >> 3;
        b_base[half] = uB + lb_k * 256 + ((u ^ (lb_k & 7)) << 4);
    }

    const __half* Wb = Wglob + (size_t)e * Dd * Hh;

    auto issue = [&](int kt) {
        int buf = kt & (NST - 1);
        uint32_t ab = uA + buf * A_BY;
        uint32_t bb = uB + buf * B_BY;
        #pragma unroll
        for (int i = 0; i < 2; i++) {                 // A: 512 x 16B chunks
            int idx = i * 256 + t;
            int r = idx >> 3, u = idx & 7;
            uint32_t dst = ab + r * 128 + ((u ^ (r & 7)) << 4);
            cp16(dst, g_hh + (size_t)(base + min(r, rows - 1)) * Hh + kt * 64 + u * 8,
                 (r < rows) ? 16 : 0);
        }
        #pragma unroll
        for (int i = 0; i < 4; i++) {                 // B: 1024 x 16B chunks
            int idx = i * 256 + t;
            int k = idx >> 4, u = idx & 15;
            uint32_t dst = bb + k * 256 + ((u ^ (k & 7)) << 4);
            cp16(dst, Wb + (size_t)(kt * 64 + k) * Dd + n0 + u * 8, 16);
        }
        asm volatile("cp.async.commit_group;" ::: "memory");
    };

    issue(0); issue(1); issue(2);

    float acc[2][4][4] = {};

    #pragma unroll 4
    for (int j = 0; j < NT; j++) {
        int buf = j & (NST - 1);
        if (j <= NT - 3)      asm volatile("cp.async.wait_group 2;" ::: "memory");
        else if (j == NT - 2) asm volatile("cp.async.wait_group 1;" ::: "memory");
        else                  asm volatile("cp.async.wait_group 0;" ::: "memory");
        __syncthreads();
        if (j + 3 < NT) issue(j + 3);

        uint32_t aoff = buf * A_BY;
        uint32_t boff = buf * B_BY;

        #pragma unroll
        for (int ks = 0; ks < 4; ks++) {
            uint32_t a[2][4];
            #pragma unroll
            for (int mi = 0; mi < 2; mi++)
                ldsm4(a[mi], a_base[mi][ks] + aoff);
            uint32_t b[2][4];
            #pragma unroll
            for (int half = 0; half < 2; half++)
                ldsm4t(b[half], b_base[half] + boff + ks * 4096);
            #pragma unroll
            for (int mi = 0; mi < 2; mi++)
                #pragma unroll
                for (int ni = 0; ni < 4; ni++)
                    mma_f16(acc[mi][ni], a[mi][0], a[mi][1], a[mi][2], a[mi][3],
                            b[ni >> 1][(ni & 1) * 2], b[ni >> 1][(ni & 1) * 2 + 1]);
        }
    }

    #pragma unroll
    for (int mi = 0; mi < 2; mi++) {
        int r0 = wm0 + mi * 16 + gid;
        #pragma unroll
        for (int ni = 0; ni < 4; ni++) {
            int c = n0 + wn0 + ni * 8 + tig * 2;
            #pragma unroll
            for (int half = 0; half < 2; half++) {
                int r = r0 + half * 8;
                if (r < rows) {
                    size_t o = (size_t)(base + r) * Dd + c;
                    g_y[o]     = acc[mi][ni][half * 2];
                    g_y[o + 1] = acc[mi][ni][half * 2 + 1];
                }
            }
        }
    }
}

#define SM1 (NST*(128*64 + 32*256) + 512)
#define SM2 (NST*(64*128 + 64*256) + 512)

// ---------------- combine (+aux, +state reset) --------------------------------
__global__ void combine_kernel(float* __restrict__ out, int out_size) {
    int idx = blockIdx.x * 256 + threadIdx.x;
    if (idx < Nn * (Dd / 4)) {
        int n = idx / (Dd / 4), q = idx - n * (Dd / 4);
        int s0 = g_tok_slot[n*2], s1 = g_tok_slot[n*2 + 1];
        float w0 = g_topw[n*2], w1 = g_topw[n*2 + 1];
        float4 y0 = *(const float4*)(g_y + (size_t)s0 * Dd + q * 4);
        float4 y1 = *(const float4*)(g_y + (size_t)s1 * Dd + q * 4);
        float4 o;
        o.x = w0 * y0.x + w1 * y1.x;
        o.y = w0 * y0.y + w1 * y1.y;
        o.z = w0 * y0.z + w1 * y1.z;
        o.w = w0 * y0.w + w1 * y1.w;
        *(float4*)(out + (size_t)n * Dd + q * 4) = o;
    }
    if (blockIdx.x == 0 && threadIdx.x == 0) {
        int extra = out_size - Nn * Dd;
        if (extra > 0) {
            float aux = 0.f;
            #pragma unroll
            for (int e = 0; e < Ee; e++) {
                float tpe = g_probsum[e] * (1.0f / (float)Nn);
                float dlt = tpe - 1.0f / (float)Ee;
                aux += dlt * dlt;
            }
            aux = 0.01f * aux / (float)Ee;
            for (int i = 0; i < extra; i++) out[Nn * Dd + i] = aux;
        }
        #pragma unroll
        for (int e = 0; e < Ee; e++) { g_counts[e] = 0; g_probsum[e] = 0.f; }
    }
}

// ---------------- launch -----------------------------------------------------
extern "C" void kernel_launch(void* const* d_in, const int* in_sizes, int n_in,
                              void* d_out, int out_size) {
    const float* x  = (const float*)d_in[0];
    const float* Wr = (const float*)d_in[1];
    const float* W1 = (const float*)d_in[2];
    const float* W2 = (const float*)d_in[3];
    float* out = (float*)d_out;

    cudaFuncSetAttribute(gemm1_kernel, cudaFuncAttributeMaxDynamicSharedMemorySize, SM1);
    cudaFuncSetAttribute(gemm2_kernel, cudaFuncAttributeMaxDynamicSharedMemorySize, SM2);

    __half* w1h; cudaGetSymbolAddress((void**)&w1h, g_w1h);
    __half* w2h; cudaGetSymbolAddress((void**)&w2h, g_w2h);

    routing_kernel<<<Nn, 128>>>(x, Wr, W1);
    gemm1_kernel<<<dim3(Hh / 128, Nn / 128, Ee), 256, SM1>>>(w1h, W2);
    gemm2_kernel<<<dim3(Dd / 128, Nn / 64, Ee), 256, SM2>>>(w2h);
    combine_kernel<<<(Nn * (Dd / 4) + 255) / 256, 256>>>(out, out_size);
}

// round 14
// speedup vs baseline: 1.4556x; 1.4556x over previous
#include <cuda_runtime.h>
#include <cuda_fp16.h>
#include <math.h>
#include <stdint.h>

#define Bb 2
#define Tt 1024
#define Dd 768
#define Hh 3072
#define Ee 8
#define Nn (Bb*Tt)      // 2048 tokens
#define NK (Nn*2)       // 4096 assignments
#define CAP Nn          // slots per expert

// ---------------- scratch (device globals) ----------------------------------
__device__ __half g_hh[(size_t)Ee * CAP * Hh];   // gelu(x@W1), fp16, slot rows
__device__ float  g_y[(size_t)Ee * CAP * Dd];    // h@W2, slot rows
__device__ __half g_xh[(size_t)Nn * Dd];         // fp16 x
__device__ __half g_w1h[(size_t)Ee * Dd * Hh];
__device__ __half g_w2h[(size_t)Ee * Dd * Hh];
__device__ int   g_counts[Ee];                   // zero at entry; reset by combine
__device__ float g_topw[NK];
__device__ int   g_slot_tok[Ee * CAP];
__device__ int   g_tok_slot[NK];
__device__ float g_probsum[Ee];                  // zero at entry; reset by combine

// ---------------- helpers ----------------------------------------------------
__device__ __forceinline__ void cp16(uint32_t dst, const void* src, int pbytes) {
    asm volatile("cp.async.cg.shared.global [%0], [%1], 16, %2;"
                 :: "r"(dst), "l"(src), "r"(pbytes));
}
__device__ __forceinline__ void mma_f16(float c[4], uint32_t a0, uint32_t a1,
                                        uint32_t a2, uint32_t a3,
                                        uint32_t b0, uint32_t b1) {
    asm volatile(
        "mma.sync.aligned.m16n8k16.row.col.f32.f16.f16.f32 "
        "{%0,%1,%2,%3}, {%4,%5,%6,%7}, {%8,%9}, {%0,%1,%2,%3};"
        : "+f"(c[0]), "+f"(c[1]), "+f"(c[2]), "+f"(c[3])
        : "r"(a0), "r"(a1), "r"(a2), "r"(a3), "r"(b0), "r"(b1));
}
__device__ __forceinline__ void ldsm4(uint32_t a[4], uint32_t addr) {
    asm volatile("ldmatrix.sync.aligned.m8n8.x4.shared.b16 {%0,%1,%2,%3}, [%4];"
                 : "=r"(a[0]), "=r"(a[1]), "=r"(a[2]), "=r"(a[3]) : "r"(addr));
}
__device__ __forceinline__ void ldsm4t(uint32_t a[4], uint32_t addr) {
    asm volatile("ldmatrix.sync.aligned.m8n8.x4.trans.shared.b16 {%0,%1,%2,%3}, [%4];"
                 : "=r"(a[0]), "=r"(a[1]), "=r"(a[2]), "=r"(a[3]) : "r"(addr));
}
__device__ __forceinline__ float gelu_exact(float c) {
    return 0.5f * c * (1.f + erff(c * 0.7071067811865475f));
}
__device__ __forceinline__ uint32_t pack2(float a, float b) {
    __half2 h = __floats2half2_rn(a, b);
    return *reinterpret_cast<uint32_t*>(&h);
}
// convert one 16B quad (8 fp32 -> 8 fp16)
__device__ __forceinline__ void conv_quad(const float* __restrict__ src,
                                          __half* __restrict__ dst, long long q) {
    const float4* s = reinterpret_cast<const float4*>(src) + q * 2;
    float4 v0 = s[0], v1 = s[1];
    uint4 o;
    o.x = pack2(v0.x, v0.y); o.y = pack2(v0.z, v0.w);
    o.z = pack2(v1.x, v1.y); o.w = pack2(v1.z, v1.w);
    reinterpret_cast<uint4*>(dst)[q] = o;
}

// ---------------- routing (+x fp16, +W1 fp16) --------------------------------
__global__ void routing_kernel(const float* __restrict__ x,
                               const float* __restrict__ Wr,
                               const float* __restrict__ W1) {
    int n = blockIdx.x;
    int t = threadIdx.x;
    const float* xr = x + (size_t)n * Dd;
    float a0 = 0.f, a1 = 0.f, a2 = 0.f;
    for (int d = t; d < Dd; d += 128) {
        float xv = xr[d];
        g_xh[(size_t)n * Dd + d] = __float2half(xv);
        a0 += xv * Wr[d];
        a1 += xv * Wr[Dd + d];
        a2 += xv * Wr[2 * Dd + d];
    }
    __shared__ float s0[128], s1[128], s2[128];
    s0[t] = a0; s1[t] = a1; s2[t] = a2;
    __syncthreads();
    for (int off = 64; off > 0; off >>= 1) {
        if (t < off) { s0[t] += s0[t+off]; s1[t] += s1[t+off]; s2[t] += s2[t+off]; }
        __syncthreads();
    }
    if (t == 0) {
        float z0 = s0[0], z1 = s1[0], z2 = s2[0];
        const float inv3 = 0.57735026918962576f;
        float logits[Ee];
        #pragma unroll
        for (int e = 0; e < Ee; e++) {
            float d0 = (e & 4) ? 1.f : -1.f;
            float d1 = (e & 2) ? 1.f : -1.f;
            float d2 = (e & 1) ? 1.f : -1.f;
            logits[e] = (d0 * z0 + d1 * z1 + d2 * z2) * inv3;
        }
        float m = logits[0];
        #pragma unroll
        for (int e = 1; e < Ee; e++) m = fmaxf(m, logits[e]);
        float p[Ee]; float sum = 0.f;
        #pragma unroll
        for (int e = 0; e < Ee; e++) { p[e] = expf(logits[e] - m); sum += p[e]; }
        float invs = 1.f / sum;
        #pragma unroll
        for (int e = 0; e < Ee; e++) atomicAdd(&g_probsum[e], p[e] * invs);
        int i0 = 0;
        #pragma unroll
        for (int e = 1; e < Ee; e++) if (p[e] > p[i0]) i0 = e;
        int i1 = (i0 == 0) ? 1 : 0;
        #pragma unroll
        for (int e = 0; e < Ee; e++) if (e != i0 && p[e] > p[i1]) i1 = e;
        float v0 = p[i0], v1 = p[i1];
        float wd = 1.f / (v0 + v1);
        g_topw[n*2]   = v0 * wd; g_topw[n*2+1] = v1 * wd;
        int pos0 = atomicAdd(&g_counts[i0], 1);
        int pos1 = atomicAdd(&g_counts[i1], 1);
        int slot0 = i0 * CAP + pos0;
        int slot1 = i1 * CAP + pos1;
        g_slot_tok[slot0] = n;  g_tok_slot[n*2]     = slot0;
        g_slot_tok[slot1] = n;  g_tok_slot[n*2 + 1] = slot1;
    }
    long long qbase = (long long)n * 1152;
    #pragma unroll
    for (int q = 0; q < 9; q++)
        conv_quad(W1, g_w1h, qbase + q * 128 + t);
}

// ---------------- gemm1: 128x128, BK=32 (proven; also converts W2) -----------
#define NST 4

__global__ __launch_bounds__(256, 2) void gemm1_kernel(const __half* __restrict__ Wglob,
                                                       const float* __restrict__ W2src) {
    constexpr int A_BY = 128 * 64;
    constexpr int B_BY = 32 * 256;
    constexpr int NT   = Dd / 32;        // 24

    int t = threadIdx.x;
    {
        int bid = blockIdx.x + gridDim.x * (blockIdx.y + gridDim.y * blockIdx.z);
        long long qbase = (long long)bid * 768;
        #pragma unroll
        for (int q = 0; q < 3; q++)
            conv_quad(W2src, g_w2h, qbase + q * 256 + t);
    }

    int e = blockIdx.z;
    int cnt = g_counts[e];
    int m0 = blockIdx.y * 128;
    if (m0 >= cnt) return;
    int n0 = blockIdx.x * 128;
    int base = e * CAP + m0;
    int rows = min(128, cnt - m0);

    extern __shared__ char sm[];
    uint32_t uA = (uint32_t)__cvta_generic_to_shared(sm);
    uint32_t uB = uA + NST * A_BY;
    int* stok = (int*)(sm + NST * (A_BY + B_BY));

    int wid = t >> 5, lane = t & 31;
    int wm0 = (wid & 1) * 64, wn0 = (wid >> 1) * 32;
    int gid = lane >> 2, tig = lane & 3;

    int la_r = (lane & 7) + ((lane >> 3) & 1) * 8;
    int la_u = (lane >> 4) & 1;
    int lb_k = ((lane >> 3) & 1) * 8 + (lane & 7);
    int lb_n = ((lane >> 4) & 1) * 8;

    uint32_t a_base[4][2];
    #pragma unroll
    for (int mi = 0; mi < 4; mi++) {
        int r = wm0 + mi * 16 + la_r;
        #pragma unroll
        for (int ks = 0; ks < 2; ks++) {
            int u = 2 * ks + la_u;
            a_base[mi][ks] = uA + r * 64 + ((u ^ ((r >> 1) & 3)) << 4);
        }
    }
    uint32_t b_base[2];
    #pragma unroll
    for (int half = 0; half < 2; half++) {
        int ncol = wn0 + half * 16 + lb_n;
        int u = ncol >> 3;
        b_base[half] = uB + lb_k * 256 + ((u ^ (lb_k & 7)) << 4);
    }

    const __half* Wb = Wglob + (size_t)e * Dd * Hh;

    if (t < 128) stok[t] = (t < rows) ? g_slot_tok[base + t] : -1;
    __syncthreads();

    auto issue = [&](int kt) {
        int buf = kt & (NST - 1);
        uint32_t ab = uA + buf * A_BY;
        uint32_t bb = uB + buf * B_BY;
        #pragma unroll
        for (int i = 0; i < 2; i++) {
            int idx = i * 256 + t;
            int r = idx >> 2, u = idx & 3;
            uint32_t dst = ab + r * 64 + ((u ^ ((r >> 1) & 3)) << 4);
            int tok = stok[r];
            cp16(dst, g_xh + (size_t)max(tok, 0) * Dd + kt * 32 + u * 8,
                 (tok >= 0) ? 16 : 0);
        }
        #pragma unroll
        for (int i = 0; i < 2; i++) {
            int idx = i * 256 + t;
            int k = idx >> 4, u = idx & 15;
            uint32_t dst = bb + k * 256 + ((u ^ (k & 7)) << 4);
            cp16(dst, Wb + (size_t)(kt * 32 + k) * Hh + n0 + u * 8, 16);
        }
        asm volatile("cp.async.commit_group;" ::: "memory");
    };

    issue(0); issue(1); issue(2);

    float acc[4][4][4] = {};

    #pragma unroll 4
    for (int j = 0; j < NT; j++) {
        int buf = j & (NST - 1);
        if (j <= NT - 3)      asm volatile("cp.async.wait_group 2;" ::: "memory");
        else if (j == NT - 2) asm volatile("cp.async.wait_group 1;" ::: "memory");
        else                  asm volatile("cp.async.wait_group 0;" ::: "memory");
        __syncthreads();
        if (j + 3 < NT) issue(j + 3);

        uint32_t aoff = buf * A_BY;
        uint32_t boff = buf * B_BY;

        #pragma unroll
        for (int ks = 0; ks < 2; ks++) {
            uint32_t a[4][4];
            #pragma unroll
            for (int mi = 0; mi < 4; mi++)
                ldsm4(a[mi], a_base[mi][ks] + aoff);
            uint32_t b[2][4];
            #pragma unroll
            for (int half = 0; half < 2; half++)
                ldsm4t(b[half], b_base[half] + boff + ks * 4096);
            #pragma unroll
            for (int mi = 0; mi < 4; mi++)
                #pragma unroll
                for (int ni = 0; ni < 4; ni++)
                    mma_f16(acc[mi][ni], a[mi][0], a[mi][1], a[mi][2], a[mi][3],
                            b[ni >> 1][(ni & 1) * 2], b[ni >> 1][(ni & 1) * 2 + 1]);
        }
    }

    #pragma unroll
    for (int mi = 0; mi < 4; mi++) {
        int r0 = wm0 + mi * 16 + gid;
        #pragma unroll
        for (int ni = 0; ni < 4; ni++) {
            int c = n0 + wn0 + ni * 8 + tig * 2;
            #pragma unroll
            for (int half = 0; half < 2; half++) {
                int r = r0 + half * 8;
                if (r < rows)
                    *(__half2*)(g_hh + (size_t)(base + r) * Hh + c) =
                        __floats2half2_rn(gelu_exact(acc[mi][ni][half * 2]),
                                          gelu_exact(acc[mi][ni][half * 2 + 1]));
            }
        }
    }
}

// ---------------- gemm2: 64x128, BK=64, NST=3, XOR-addressed A ---------------
// A addr identity: u = 2*ks + la_u (bit0=la_u, bits1-2=2ks), so
// addr(ks) = addr(0) ^ (ks << 5). a_base needs only 2 regs.
#define NST2 3

__global__ __launch_bounds__(256, 2) void gemm2_kernel(const __half* __restrict__ Wglob) {
    constexpr int A_BY = 64 * 128;       // 8 KB per stage
    constexpr int B_BY = 64 * 256;       // 16 KB per stage
    constexpr int NT   = Hh / 64;        // 48

    int e = blockIdx.z;
    int cnt = g_counts[e];
    int m0 = blockIdx.y * 64;
    if (m0 >= cnt) return;
    int n0 = blockIdx.x * 128;
    int base = e * CAP + m0;
    int rows = min(64, cnt - m0);

    extern __shared__ char sm[];
    uint32_t uA = (uint32_t)__cvta_generic_to_shared(sm);
    uint32_t uB = uA + NST2 * A_BY;

    int t = threadIdx.x, wid = t >> 5, lane = t & 31;
    int wm0 = (wid & 1) * 32, wn0 = (wid >> 1) * 32;
    int gid = lane >> 2, tig = lane & 3;

    int la_r = (lane & 7) + ((lane >> 3) & 1) * 8;
    int la_u = (lane >> 4) & 1;
    int lb_k = ((lane >> 3) & 1) * 8 + (lane & 7);
    int lb_n = ((lane >> 4) & 1) * 8;

    uint32_t a_base[2];                  // ks=0 address; others via ^(ks<<5)
    #pragma unroll
    for (int mi = 0; mi < 2; mi++) {
        int r = wm0 + mi * 16 + la_r;
        a_base[mi] = uA + r * 128 + ((la_u ^ (r & 7)) << 4);
    }
    uint32_t b_base[2];
    #pragma unroll
    for (int half = 0; half < 2; half++) {
        int ncol = wn0 + half * 16 + lb_n;
        int u = ncol >> 3;
        b_base[half] = uB + lb_k * 256 + ((u ^ (lb_k & 7)) << 4);
    }

    const __half* Wb = Wglob + (size_t)e * Dd * Hh;

    auto issue = [&](int kt) {
        int buf = kt % NST2;
        uint32_t ab = uA + buf * A_BY;
        uint32_t bb = uB + buf * B_BY;
        #pragma unroll
        for (int i = 0; i < 2; i++) {                 // A: 512 x 16B chunks
            int idx = i * 256 + t;
            int r = idx >> 3, u = idx & 7;
            uint32_t dst = ab + r * 128 + ((u ^ (r & 7)) << 4);
            cp16(dst, g_hh + (size_t)(base + min(r, rows - 1)) * Hh + kt * 64 + u * 8,
                 (r < rows) ? 16 : 0);
        }
        #pragma unroll
        for (int i = 0; i < 4; i++) {                 // B: 1024 x 16B chunks
            int idx = i * 256 + t;
            int k = idx >> 4, u = idx & 15;
            uint32_t dst = bb + k * 256 + ((u ^ (k & 7)) << 4);
            cp16(dst, Wb + (size_t)(kt * 64 + k) * Dd + n0 + u * 8, 16);
        }
        asm volatile("cp.async.commit_group;" ::: "memory");
    };

    issue(0); issue(1);

    float acc[2][4][4] = {};

    #pragma unroll 3
    for (int j = 0; j < NT; j++) {
        int buf = j % NST2;
        if (j <= NT - 2) asm volatile("cp.async.wait_group 1;" ::: "memory");
        else             asm volatile("cp.async.wait_group 0;" ::: "memory");
        __syncthreads();
        if (j + 2 < NT) issue(j + 2);

        uint32_t aoff = buf * A_BY;
        uint32_t boff = buf * B_BY;

        #pragma unroll
        for (int ks = 0; ks < 4; ks++) {
            uint32_t a[2][4];
            #pragma unroll
            for (int mi = 0; mi < 2; mi++)
                ldsm4(a[mi], (a_base[mi] + aoff) ^ (ks << 5));
            uint32_t b[2][4];
            #pragma unroll
            for (int half = 0; half < 2; half++)
                ldsm4t(b[half], b_base[half] + boff + ks * 4096);
            #pragma unroll
            for (int mi = 0; mi < 2; mi++)
                #pragma unroll
                for (int ni = 0; ni < 4; ni++)
                    mma_f16(acc[mi][ni], a[mi][0], a[mi][1], a[mi][2], a[mi][3],
                            b[ni >> 1][(ni & 1) * 2], b[ni >> 1][(ni & 1) * 2 + 1]);
        }
    }

    #pragma unroll
    for (int mi = 0; mi < 2; mi++) {
        int r0 = wm0 + mi * 16 + gid;
        #pragma unroll
        for (int ni = 0; ni < 4; ni++) {
            int c = n0 + wn0 + ni * 8 + tig * 2;
            #pragma unroll
            for (int half = 0; half < 2; half++) {
                int r = r0 + half * 8;
                if (r < rows) {
                    size_t o = (size_t)(base + r) * Dd + c;
                    g_y[o]     = acc[mi][ni][half * 2];
                    g_y[o + 1] = acc[mi][ni][half * 2 + 1];
                }
            }
        }
    }
}

#define SM1 (NST*(128*64 + 32*256) + 512)
#define SM2 (NST2*(64*128 + 64*256) + 512)

// ---------------- combine (+aux, +state reset) --------------------------------
__global__ void combine_kernel(float* __restrict__ out, int out_size) {
    int idx = blockIdx.x * 256 + threadIdx.x;
    if (idx < Nn * (Dd / 4)) {
        int n = idx / (Dd / 4), q = idx - n * (Dd / 4);
        int s0 = g_tok_slot[n*2], s1 = g_tok_slot[n*2 + 1];
        float w0 = g_topw[n*2], w1 = g_topw[n*2 + 1];
        float4 y0 = *(const float4*)(g_y + (size_t)s0 * Dd + q * 4);
        float4 y1 = *(const float4*)(g_y + (size_t)s1 * Dd + q * 4);
        float4 o;
        o.x = w0 * y0.x + w1 * y1.x;
        o.y = w0 * y0.y + w1 * y1.y;
        o.z = w0 * y0.z + w1 * y1.z;
        o.w = w0 * y0.w + w1 * y1.w;
        *(float4*)(out + (size_t)n * Dd + q * 4) = o;
    }
    if (blockIdx.x == 0 && threadIdx.x == 0) {
        int extra = out_size - Nn * Dd;
        if (extra > 0) {
            float aux = 0.f;
            #pragma unroll
            for (int e = 0; e < Ee; e++) {
                float tpe = g_probsum[e] * (1.0f / (float)Nn);
                float dlt = tpe - 1.0f / (float)Ee;
                aux += dlt * dlt;
            }
            aux = 0.01f * aux / (float)Ee;
            for (int i = 0; i < extra; i++) out[Nn * Dd + i] = aux;
        }
        #pragma unroll
        for (int e = 0; e < Ee; e++) { g_counts[e] = 0; g_probsum[e] = 0.f; }
    }
}

// ---------------- launch -----------------------------------------------------
extern "C" void kernel_launch(void* const* d_in, const int* in_sizes, int n_in,
                              void* d_out, int out_size) {
    const float* x  = (const float*)d_in[0];
    const float* Wr = (const float*)d_in[1];
    const float* W1 = (const float*)d_in[2];
    const float* W2 = (const float*)d_in[3];
    float* out = (float*)d_out;

    cudaFuncSetAttribute(gemm1_kernel, cudaFuncAttributeMaxDynamicSharedMemorySize, SM1);
    cudaFuncSetAttribute(gemm2_kernel, cudaFuncAttributeMaxDynamicSharedMemorySize, SM2);

    __half* w1h; cudaGetSymbolAddress((void**)&w1h, g_w1h);
    __half* w2h; cudaGetSymbolAddress((void**)&w2h, g_w2h);

    routing_kernel<<<Nn, 128>>>(x, Wr, W1);
    gemm1_kernel<<<dim3(Hh / 128, Nn / 128, Ee), 256, SM1>>>(w1h, W2);
    gemm2_kernel<<<dim3(Dd / 128, Nn / 64, Ee), 256, SM2>>>(w2h);
    combine_kernel<<<(Nn * (Dd / 4) + 255) / 256, 256>>>(out, out_size);
}